// round 2
// baseline (speedup 1.0000x reference)
#include <cuda_runtime.h>

// Problem dims (fixed by the reference)
constexpr int Nn = 4096;   // z rows
constexpr int Mm = 1024;   // e rows
constexpr int Dd = 64;     // feature dim

// Scratch (no allocations allowed -> device globals)
__device__ float g_accum;
__device__ __align__(16) float g_zt[Dd * Nn];   // z transposed: [D][N], 1 MB

// ---------------------------------------------------------------------------
// Zero the accumulator (graph replays need this every launch)
__global__ void k_zero() { g_accum = 0.0f; }

// ---------------------------------------------------------------------------
// Transpose z [N, D] -> g_zt [D, N] so the min kernel loads columns coalesced.
__global__ void k_transpose(const float* __restrict__ z) {
    __shared__ float tile[32][33];
    int x = blockIdx.x * 32 + threadIdx.x;   // D index
    int y = blockIdx.y * 32 + threadIdx.y;   // N index
    tile[threadIdx.y][threadIdx.x] = z[y * Dd + x];
    __syncthreads();
    int tx = blockIdx.y * 32 + threadIdx.x;  // N index (output inner)
    int ty = blockIdx.x * 32 + threadIdx.y;  // D index (output outer)
    g_zt[ty * Nn + tx] = tile[threadIdx.x][threadIdx.y];
}

// ---------------------------------------------------------------------------
// For column d = blockIdx.x, m-chunk = blockIdx.y (128 m's per chunk):
// each thread owns one m; computes min_n |z[n,d] - e[m,d]|, squares it,
// block-reduces the sum, atomicAdd into g_accum.
__global__ void __launch_bounds__(128, 8) k_min(const float* __restrict__ e) {
    __shared__ float zs[Nn];          // 16 KB: column d of z
    __shared__ float wsum[4];

    const int d = blockIdx.x;
    const int t = threadIdx.x;

    // Coalesced column load (float4)
    {
        const float4* src = reinterpret_cast<const float4*>(g_zt + d * Nn);
        float4* dst = reinterpret_cast<float4*>(zs);
        #pragma unroll
        for (int i = t; i < Nn / 4; i += 128) dst[i] = src[i];
    }
    __syncthreads();

    const int m = blockIdx.y * 128 + t;
    const float x = e[m * Dd + d];

    // 8 independent min chains to hide FMNMX latency
    float a0 = 1e30f, a1 = 1e30f, a2 = 1e30f, a3 = 1e30f;
    float a4 = 1e30f, a5 = 1e30f, a6 = 1e30f, a7 = 1e30f;

    const float4* zv = reinterpret_cast<const float4*>(zs);
    #pragma unroll 4
    for (int i = 0; i < Nn / 4; i += 2) {
        float4 p = zv[i];
        float4 q = zv[i + 1];
        a0 = fminf(a0, fabsf(p.x - x));
        a1 = fminf(a1, fabsf(p.y - x));
        a2 = fminf(a2, fabsf(p.z - x));
        a3 = fminf(a3, fabsf(p.w - x));
        a4 = fminf(a4, fabsf(q.x - x));
        a5 = fminf(a5, fabsf(q.y - x));
        a6 = fminf(a6, fabsf(q.z - x));
        a7 = fminf(a7, fabsf(q.w - x));
    }
    a0 = fminf(a0, a1); a2 = fminf(a2, a3);
    a4 = fminf(a4, a5); a6 = fminf(a6, a7);
    a0 = fminf(a0, a2); a4 = fminf(a4, a6);
    float mm = fminf(a0, a4);
    float val = mm * mm;               // min_n (z - x)^2

    // Block sum reduction
    #pragma unroll
    for (int o = 16; o > 0; o >>= 1)
        val += __shfl_xor_sync(0xFFFFFFFFu, val, o);
    const int lane = t & 31, wid = t >> 5;
    if (lane == 0) wsum[wid] = val;
    __syncthreads();
    if (t == 0) {
        float s = wsum[0] + wsum[1] + wsum[2] + wsum[3];
        atomicAdd(&g_accum, s);
    }
}

// ---------------------------------------------------------------------------
__global__ void k_finalize(float* __restrict__ out) {
    out[0] = g_accum * (1.0f / float(Mm * Dd));
}

// ---------------------------------------------------------------------------
// z_masked[i][j] = z[i][j] * (j < idx[i]); z_copy = z.
// NOTE: zmask/zcopy are offset by the scalar loss -> only 4-byte aligned.
// Loads from z use float4 (z is 16B-aligned); stores are scalar STG.32.
__global__ void k_mask(const float* __restrict__ z, const int* __restrict__ idx,
                       float* __restrict__ zmask, float* __restrict__ zcopy) {
    int gid = blockIdx.x * blockDim.x + threadIdx.x;   // over N*D/4
    if (gid >= Nn * Dd / 4) return;
    int row = gid >> 4;                 // 16 float4 per row (D=64)
    int j0 = (gid & 15) * 4;
    float4 v = reinterpret_cast<const float4*>(z)[gid];
    int k = idx[row];
    int base = gid * 4;
    zcopy[base + 0] = v.x;
    zcopy[base + 1] = v.y;
    zcopy[base + 2] = v.z;
    zcopy[base + 3] = v.w;
    zmask[base + 0] = (j0 + 0 < k) ? v.x : 0.0f;
    zmask[base + 1] = (j0 + 1 < k) ? v.y : 0.0f;
    zmask[base + 2] = (j0 + 2 < k) ? v.z : 0.0f;
    zmask[base + 3] = (j0 + 3 < k) ? v.w : 0.0f;
}

// ---------------------------------------------------------------------------
extern "C" void kernel_launch(void* const* d_in, const int* in_sizes, int n_in,
                              void* d_out, int out_size) {
    const float* z  = (const float*)d_in[0];
    const float* e  = (const float*)d_in[1];
    const int* idx  = (const int*)d_in[2];
    float* out = (float*)d_out;
    float* zmask = out + 1;
    float* zcopy = out + 1 + Nn * Dd;

    k_zero<<<1, 1>>>();
    k_transpose<<<dim3(Dd / 32, Nn / 32), dim3(32, 32)>>>(z);
    k_min<<<dim3(Dd, Mm / 128), 128>>>(e);
    k_finalize<<<1, 1>>>(out);
    k_mask<<<(Nn * Dd / 4 + 255) / 256, 256>>>(z, idx, zmask, zcopy);
}

// round 3
// speedup vs baseline: 1.0514x; 1.0514x over previous
#include <cuda_runtime.h>

constexpr int Nn = 4096;   // z rows
constexpr int Mm = 1024;   // e rows
constexpr int Dd = 64;     // feature dim

constexpr int   BK   = 2048;                 // buckets per column
constexpr float LOb  = -6.0f;
constexpr float HIb  =  6.0f;
constexpr float Wb   = (HIb - LOb) / BK;     // bucket width
constexpr float INVW = BK / (HIb - LOb);

// Scratch (no allocations allowed -> device globals)
__device__ __align__(16) float g_zt[Dd * Nn];   // z transposed: [D][N]

// ---------------------------------------------------------------------------
// k1: fused transpose + mask + copy + zero-loss.
// Grid (Dd/32, Nn/32), block (32,32). Each thread handles one z element.
__global__ void k1_prep(const float* __restrict__ z, const int* __restrict__ idx,
                        float* __restrict__ out) {
    __shared__ float tile[32][33];
    int x = blockIdx.x * 32 + threadIdx.x;   // D index
    int y = blockIdx.y * 32 + threadIdx.y;   // N index
    float v = z[y * Dd + x];
    tile[threadIdx.y][threadIdx.x] = v;

    // mask + copy (scalar stores: out+1 region is only 4B aligned)
    int k = idx[y];                          // broadcast within warp
    out[1 + y * Dd + x]            = (x < k) ? v : 0.0f;   // z_masked
    out[1 + Nn * Dd + y * Dd + x]  = v;                    // z_copy

    if (blockIdx.x == 0 && blockIdx.y == 0 && threadIdx.x == 0 && threadIdx.y == 0)
        out[0] = 0.0f;                       // loss accumulator (before k2)

    __syncthreads();
    int tx = blockIdx.y * 32 + threadIdx.x;  // N index (output inner)
    int ty = blockIdx.x * 32 + threadIdx.y;  // D index (output outer)
    g_zt[ty * Nn + tx] = tile[threadIdx.x][threadIdx.y];
}

// ---------------------------------------------------------------------------
// k2: per-column 1-D nearest neighbor via bucket sort + ring search.
// One block per column d (64 blocks, 1024 threads).
__global__ void __launch_bounds__(1024, 1) k2_nn(const float* __restrict__ e,
                                                 float* __restrict__ out) {
    __shared__ float S[Nn];          // bucket-sorted column values (16 KB)
    __shared__ int   off[BK + 1];    // exclusive prefix offsets (8 KB)
    __shared__ int   cnt[BK];        // histogram / scatter cursors (8 KB)
    __shared__ int   wtot[32];
    __shared__ float red[32];

    const int d = blockIdx.x;
    const int t = threadIdx.x;
    const int lane = t & 31, wid = t >> 5;

    // ---- histogram ----
    cnt[t] = 0; cnt[t + 1024] = 0;
    __syncthreads();

    float v[4]; int bk[4];
    #pragma unroll
    for (int i = 0; i < 4; i++) {
        v[i] = g_zt[d * Nn + t + i * 1024];                 // coalesced
        int k = (int)((v[i] - LOb) * INVW);
        k = min(max(k, 0), BK - 1);
        bk[i] = k;
        atomicAdd(&cnt[k], 1);
    }
    __syncthreads();

    // ---- block exclusive scan over cnt[0..BK-1] (2 buckets per thread) ----
    int c0 = cnt[2 * t], c1 = cnt[2 * t + 1];
    int s = c0 + c1;
    int inc = s;
    #pragma unroll
    for (int o = 1; o < 32; o <<= 1) {
        int n = __shfl_up_sync(0xFFFFFFFFu, inc, o);
        if (lane >= o) inc += n;
    }
    if (lane == 31) wtot[wid] = inc;
    __syncthreads();
    if (wid == 0) {
        int ws = wtot[lane];
        int wi = ws;
        #pragma unroll
        for (int o = 1; o < 32; o <<= 1) {
            int n = __shfl_up_sync(0xFFFFFFFFu, wi, o);
            if (lane >= o) wi += n;
        }
        wtot[lane] = wi - ws;            // exclusive warp offsets
    }
    __syncthreads();
    int excl = (inc - s) + wtot[wid];    // exclusive prefix of this thread's pair
    off[2 * t]     = excl;
    off[2 * t + 1] = excl + c0;
    if (t == 1023) off[BK] = excl + s;   // == Nn
    __syncthreads();

    // ---- scatter (cnt becomes running cursor) ----
    cnt[2 * t] = off[2 * t];
    cnt[2 * t + 1] = off[2 * t + 1];
    __syncthreads();
    #pragma unroll
    for (int i = 0; i < 4; i++) {
        int p = atomicAdd(&cnt[bk[i]], 1);
        S[p] = v[i];
    }
    __syncthreads();

    // ---- query: thread t handles m = t ----
    float x = e[t * Dd + d];
    int k0 = min(max((int)((x - LOb) * INVW), 0), BK - 1);
    float best = 1e30f;
    for (int j = off[k0]; j < off[k0 + 1]; j++)
        best = fminf(best, fabsf(S[j] - x));
    for (int r = 1; ; r++) {
        if (best <= (float)(r - 1) * Wb) break;   // ring lower bound (exact)
        int kl = k0 - r, kr = k0 + r;
        bool any = false;
        if (kl >= 0) {
            any = true;
            for (int j = off[kl]; j < off[kl + 1]; j++)
                best = fminf(best, fabsf(S[j] - x));
        }
        if (kr < BK) {
            any = true;
            for (int j = off[kr]; j < off[kr + 1]; j++)
                best = fminf(best, fabsf(S[j] - x));
        }
        if (!any) break;                          // entire array scanned
    }

    float val = best * best * (1.0f / (float)(Mm * Dd));

    // ---- block sum reduce + single atomicAdd ----
    #pragma unroll
    for (int o = 16; o > 0; o >>= 1)
        val += __shfl_xor_sync(0xFFFFFFFFu, val, o);
    if (lane == 0) red[wid] = val;
    __syncthreads();
    if (wid == 0) {
        float sv = red[lane];
        #pragma unroll
        for (int o = 16; o > 0; o >>= 1)
            sv += __shfl_xor_sync(0xFFFFFFFFu, sv, o);
        if (lane == 0) atomicAdd(out, sv);
    }
}

// ---------------------------------------------------------------------------
extern "C" void kernel_launch(void* const* d_in, const int* in_sizes, int n_in,
                              void* d_out, int out_size) {
    const float* z = (const float*)d_in[0];
    const float* e = (const float*)d_in[1];
    const int* idx = (const int*)d_in[2];
    float* out = (float*)d_out;

    k1_prep<<<dim3(Dd / 32, Nn / 32), dim3(32, 32)>>>(z, idx, out);
    k2_nn<<<Dd, 1024>>>(e, out);
}

// round 5
// speedup vs baseline: 1.4794x; 1.4071x over previous
#include <cuda_runtime.h>

constexpr int Nn = 4096;   // z rows
constexpr int Mm = 1024;   // e rows
constexpr int Dd = 64;     // feature dim

constexpr int   BK   = 4096;                 // buckets per column
constexpr float LOb  = -6.0f;
constexpr float HIb  =  6.0f;
constexpr float INVW = BK / (HIb - LOb);

// Scratch (no allocations allowed -> device globals)
__device__ __align__(16) float g_zt[Dd * Nn];   // z transposed: [D][N]

// ---------------------------------------------------------------------------
// k1: fused transpose + mask + copy + zero-loss.
__global__ void k1_prep(const float* __restrict__ z, const int* __restrict__ idx,
                        float* __restrict__ out) {
    __shared__ float tile[32][33];
    int x = blockIdx.x * 32 + threadIdx.x;   // D index
    int y = blockIdx.y * 32 + threadIdx.y;   // N index
    float v = z[y * Dd + x];
    tile[threadIdx.y][threadIdx.x] = v;

    int k = idx[y];
    out[1 + y * Dd + x]           = (x < k) ? v : 0.0f;   // z_masked
    out[1 + Nn * Dd + y * Dd + x] = v;                    // z_copy

    if (blockIdx.x == 0 && blockIdx.y == 0 && threadIdx.x == 0 && threadIdx.y == 0)
        out[0] = 0.0f;

    __syncthreads();
    int tx = blockIdx.y * 32 + threadIdx.x;  // N index (output inner)
    int ty = blockIdx.x * 32 + threadIdx.y;  // D index (output outer)
    g_zt[ty * Nn + tx] = tile[threadIdx.x][threadIdx.y];
}

// ---------------------------------------------------------------------------
// k2: per-column 1-D NN. Bucket sort -> per-bucket insertion sort (global
// sorted order) -> branchless binary search per query. One block per column.
// cnt[] serves three roles: histogram -> exclusive-prefix cursor -> inclusive
// bucket end (after scatter). No separate off[] array (smem limit).
__global__ void __launch_bounds__(1024, 1) k2_nn(const float* __restrict__ e,
                                                 float* __restrict__ out) {
    __shared__ float S[Nn];          // sorted column values (16 KB)
    __shared__ int   cnt[BK];        // hist / cursor / bucket ends (16 KB)
    __shared__ int   wtot[32];
    __shared__ float red[32];

    const int d = blockIdx.x;
    const int t = threadIdx.x;
    const int lane = t & 31, wid = t >> 5;

    // ---- histogram ----
    #pragma unroll
    for (int i = 0; i < 4; i++) cnt[t + i * 1024] = 0;
    __syncthreads();

    float v[4]; int bk[4];
    #pragma unroll
    for (int i = 0; i < 4; i++) {
        v[i] = g_zt[d * Nn + t + i * 1024];                 // coalesced
        int k = (int)((v[i] - LOb) * INVW);
        k = min(max(k, 0), BK - 1);
        bk[i] = k;
        atomicAdd(&cnt[k], 1);
    }
    __syncthreads();

    // ---- block exclusive scan over cnt[0..BK-1] (4 buckets per thread) ----
    int c0 = cnt[4 * t], c1 = cnt[4 * t + 1], c2 = cnt[4 * t + 2], c3 = cnt[4 * t + 3];
    int s = c0 + c1 + c2 + c3;
    int inc = s;
    #pragma unroll
    for (int o = 1; o < 32; o <<= 1) {
        int n = __shfl_up_sync(0xFFFFFFFFu, inc, o);
        if (lane >= o) inc += n;
    }
    if (lane == 31) wtot[wid] = inc;
    __syncthreads();
    if (wid == 0) {
        int ws = wtot[lane];
        int wi = ws;
        #pragma unroll
        for (int o = 1; o < 32; o <<= 1) {
            int n = __shfl_up_sync(0xFFFFFFFFu, wi, o);
            if (lane >= o) wi += n;
        }
        wtot[lane] = wi - ws;            // exclusive warp offsets
    }
    __syncthreads();
    int excl = (inc - s) + wtot[wid];    // exclusive prefix of this thread's group
    cnt[4 * t]     = excl;
    cnt[4 * t + 1] = excl + c0;
    cnt[4 * t + 2] = excl + c0 + c1;
    cnt[4 * t + 3] = excl + c0 + c1 + c2;
    __syncthreads();

    // ---- scatter: cursors advance from exclusive start to inclusive end ----
    #pragma unroll
    for (int i = 0; i < 4; i++) {
        int p = atomicAdd(&cnt[bk[i]], 1);
        S[p] = v[i];
    }
    __syncthreads();     // now cnt[b] == inclusive end of bucket b

    // ---- per-bucket insertion sort (thread t owns buckets 4t..4t+3) ----
    #pragma unroll
    for (int b4 = 0; b4 < 4; b4++) {
        int b = 4 * t + b4;
        int lo = (b == 0) ? 0 : cnt[b - 1];
        int hi = cnt[b];
        for (int i = lo + 1; i < hi; i++) {
            float key = S[i];
            int j = i - 1;
            while (j >= lo && S[j] > key) { S[j + 1] = S[j]; j--; }
            S[j + 1] = key;
        }
    }
    __syncthreads();

    // ---- query: branchless lower-bound binary search over sorted S ----
    float x = e[t * Dd + d];
    int pos = 0;                         // count of elements < x
    #pragma unroll
    for (int step = 4096; step >= 1; step >>= 1) {
        int np = pos + step;
        if (np <= Nn && S[np - 1] < x) pos = np;
    }
    float best = 1e30f;
    if (pos < Nn) best = S[pos] - x;           // >= 0 by construction
    if (pos > 0)  best = fminf(best, x - S[pos - 1]);

    float val = best * best * (1.0f / (float)(Mm * Dd));

    // ---- block sum reduce + single atomicAdd ----
    #pragma unroll
    for (int o = 16; o > 0; o >>= 1)
        val += __shfl_xor_sync(0xFFFFFFFFu, val, o);
    if (lane == 0) red[wid] = val;
    __syncthreads();
    if (wid == 0) {
        float sv = red[lane];
        #pragma unroll
        for (int o = 16; o > 0; o >>= 1)
            sv += __shfl_xor_sync(0xFFFFFFFFu, sv, o);
        if (lane == 0) atomicAdd(out, sv);
    }
}

// ---------------------------------------------------------------------------
extern "C" void kernel_launch(void* const* d_in, const int* in_sizes, int n_in,
                              void* d_out, int out_size) {
    const float* z = (const float*)d_in[0];
    const float* e = (const float*)d_in[1];
    const int* idx = (const int*)d_in[2];
    float* out = (float*)d_out;

    k1_prep<<<dim3(Dd / 32, Nn / 32), dim3(32, 32)>>>(z, idx, out);
    k2_nn<<<Dd, 1024>>>(e, out);
}

// round 6
// speedup vs baseline: 2.7091x; 1.8312x over previous
#include <cuda_runtime.h>

constexpr int Nn = 4096;   // z rows
constexpr int Mm = 1024;   // e rows
constexpr int Dd = 64;     // feature dim

constexpr int   BK   = 4096;                 // buckets per column
constexpr float LOb  = -6.0f;
constexpr float HIb  =  6.0f;
constexpr float INVW = BK / (HIb - LOb);

__device__ __forceinline__ int bucket_of(float v) {
    int k = (int)((v - LOb) * INVW);
    return min(max(k, 0), BK - 1);
}

// Scratch (no allocations allowed -> device globals)
__device__ __align__(16) float g_zt[Dd * Nn];   // z transposed: [D][N]

// ---------------------------------------------------------------------------
// k1: fused transpose + mask + copy + zero-loss.
__global__ void k1_prep(const float* __restrict__ z, const int* __restrict__ idx,
                        float* __restrict__ out) {
    __shared__ float tile[32][33];
    int x = blockIdx.x * 32 + threadIdx.x;   // D index
    int y = blockIdx.y * 32 + threadIdx.y;   // N index
    float v = z[y * Dd + x];
    tile[threadIdx.y][threadIdx.x] = v;

    int k = idx[y];
    out[1 + y * Dd + x]           = (x < k) ? v : 0.0f;   // z_masked
    out[1 + Nn * Dd + y * Dd + x] = v;                    // z_copy

    if (blockIdx.x == 0 && blockIdx.y == 0 && threadIdx.x == 0 && threadIdx.y == 0)
        out[0] = 0.0f;

    __syncthreads();
    int tx = blockIdx.y * 32 + threadIdx.x;  // N index (output inner)
    int ty = blockIdx.x * 32 + threadIdx.y;  // D index (output outer)
    g_zt[ty * Nn + tx] = tile[threadIdx.x][threadIdx.y];
}

// ---------------------------------------------------------------------------
// k2: per-column 1-D NN via bucket sort (NO intra-bucket sort, NO binary
// search). After scatter, cnt[b] = inclusive end of bucket b's segment in S.
// Query scans its own bucket plus the nearest nonempty bucket on each side,
// located directly via the boundary elements S[start-1] / S[end].
__global__ void __launch_bounds__(1024, 1) k2_nn(const float* __restrict__ e,
                                                 float* __restrict__ out) {
    __shared__ float S[Nn];          // bucket-grouped column values (16 KB)
    __shared__ int   cnt[BK];        // hist -> cursor -> inclusive ends (16 KB)
    __shared__ int   wtot[32];
    __shared__ float red[32];

    const int d = blockIdx.x;
    const int t = threadIdx.x;
    const int lane = t & 31, wid = t >> 5;

    // ---- histogram ----
    #pragma unroll
    for (int i = 0; i < 4; i++) cnt[t + i * 1024] = 0;
    __syncthreads();

    float v[4]; int bk[4];
    #pragma unroll
    for (int i = 0; i < 4; i++) {
        v[i] = g_zt[d * Nn + t + i * 1024];                 // coalesced
        bk[i] = bucket_of(v[i]);
        atomicAdd(&cnt[bk[i]], 1);
    }
    __syncthreads();

    // ---- block exclusive scan over cnt[0..BK-1] (4 buckets per thread) ----
    int c0 = cnt[4 * t], c1 = cnt[4 * t + 1], c2 = cnt[4 * t + 2], c3 = cnt[4 * t + 3];
    int s = c0 + c1 + c2 + c3;
    int inc = s;
    #pragma unroll
    for (int o = 1; o < 32; o <<= 1) {
        int n = __shfl_up_sync(0xFFFFFFFFu, inc, o);
        if (lane >= o) inc += n;
    }
    if (lane == 31) wtot[wid] = inc;
    __syncthreads();
    if (wid == 0) {
        int ws = wtot[lane];
        int wi = ws;
        #pragma unroll
        for (int o = 1; o < 32; o <<= 1) {
            int n = __shfl_up_sync(0xFFFFFFFFu, wi, o);
            if (lane >= o) wi += n;
        }
        wtot[lane] = wi - ws;            // exclusive warp offsets
    }
    __syncthreads();
    int excl = (inc - s) + wtot[wid];    // exclusive prefix of this thread's group
    cnt[4 * t]     = excl;
    cnt[4 * t + 1] = excl + c0;
    cnt[4 * t + 2] = excl + c0 + c1;
    cnt[4 * t + 3] = excl + c0 + c1 + c2;
    __syncthreads();

    // ---- scatter: cursors advance from exclusive start to inclusive end ----
    #pragma unroll
    for (int i = 0; i < 4; i++) {
        int p = atomicAdd(&cnt[bk[i]], 1);
        S[p] = v[i];
    }
    __syncthreads();     // now cnt[b] == inclusive end of bucket b

    // ---- query: own bucket + nearest nonempty bucket on each side ----
    float x = e[t * Dd + d];
    int k0 = bucket_of(x);
    int start = (k0 == 0) ? 0 : cnt[k0 - 1];
    int end   = cnt[k0];

    float best = 1e30f;
    for (int j = start; j < end; j++)
        best = fminf(best, fabsf(S[j] - x));

    if (start > 0) {                     // nearest nonempty bucket below
        float bv = S[start - 1];
        int b = bucket_of(bv);
        int lo = (b == 0) ? 0 : cnt[b - 1];
        for (int j = lo; j < start; j++)
            best = fminf(best, fabsf(S[j] - x));
    }
    if (end < Nn) {                      // nearest nonempty bucket above
        float av = S[end];
        int b = bucket_of(av);
        int hi = cnt[b];
        for (int j = end; j < hi; j++)
            best = fminf(best, fabsf(S[j] - x));
    }

    float val = best * best * (1.0f / (float)(Mm * Dd));

    // ---- block sum reduce + single atomicAdd ----
    #pragma unroll
    for (int o = 16; o > 0; o >>= 1)
        val += __shfl_xor_sync(0xFFFFFFFFu, val, o);
    if (lane == 0) red[wid] = val;
    __syncthreads();
    if (wid == 0) {
        float sv = red[lane];
        #pragma unroll
        for (int o = 16; o > 0; o >>= 1)
            sv += __shfl_xor_sync(0xFFFFFFFFu, sv, o);
        if (lane == 0) atomicAdd(out, sv);
    }
}

// ---------------------------------------------------------------------------
extern "C" void kernel_launch(void* const* d_in, const int* in_sizes, int n_in,
                              void* d_out, int out_size) {
    const float* z = (const float*)d_in[0];
    const float* e = (const float*)d_in[1];
    const int* idx = (const int*)d_in[2];
    float* out = (float*)d_out;

    k1_prep<<<dim3(Dd / 32, Nn / 32), dim3(32, 32)>>>(z, idx, out);
    k2_nn<<<Dd, 1024>>>(e, out);
}

// round 7
// speedup vs baseline: 2.9380x; 1.0845x over previous
#include <cuda_runtime.h>

constexpr int Nn = 4096;   // z rows
constexpr int Mm = 1024;   // e rows
constexpr int Dd = 64;     // feature dim

constexpr int   BK   = 4096;                 // buckets per column
constexpr float LOb  = -6.0f;
constexpr float HIb  =  6.0f;
constexpr float INVW = BK / (HIb - LOb);

__device__ __forceinline__ int bucket_of(float v) {
    int k = (int)((v - LOb) * INVW);
    return min(max(k, 0), BK - 1);
}

// Scratch (no allocations allowed -> device globals)
__device__ __align__(16) float g_zt[Dd * Nn];   // z transposed: [D][N]

// ---------------------------------------------------------------------------
// k1: fused transpose + mask + copy + zero-loss.
__global__ void k1_prep(const float* __restrict__ z, const int* __restrict__ idx,
                        float* __restrict__ out) {
    __shared__ float tile[32][33];
    int x = blockIdx.x * 32 + threadIdx.x;   // D index
    int y = blockIdx.y * 32 + threadIdx.y;   // N index
    float v = z[y * Dd + x];
    tile[threadIdx.y][threadIdx.x] = v;

    int k = idx[y];
    out[1 + y * Dd + x]           = (x < k) ? v : 0.0f;   // z_masked
    out[1 + Nn * Dd + y * Dd + x] = v;                    // z_copy

    if (blockIdx.x == 0 && blockIdx.y == 0 && threadIdx.x == 0 && threadIdx.y == 0)
        out[0] = 0.0f;

    __syncthreads();
    int tx = blockIdx.y * 32 + threadIdx.x;  // N index (output inner)
    int ty = blockIdx.x * 32 + threadIdx.y;  // D index (output outer)
    g_zt[ty * Nn + tx] = tile[threadIdx.x][threadIdx.y];
}

// ---------------------------------------------------------------------------
// k2: per-column 1-D NN via bucket grouping.
// Single atomic pass: atomicAdd on cnt[] builds the histogram AND returns each
// item's rank within its bucket. Scan converts counts -> exclusive starts
// (in place; each thread reads exactly the slots it later writes). Scatter is
// then plain stores: S[start[b] + rank]. Query scans own bucket + nearest
// nonempty bucket each side (located via boundary values). cnt[] holds STARTS;
// end of bucket b = cnt[b+1] (or Nn for b == BK-1).
__global__ void __launch_bounds__(1024, 1) k2_nn(const float* __restrict__ e,
                                                 float* __restrict__ out) {
    __shared__ float S[Nn];          // bucket-grouped column values (16 KB)
    __shared__ int   cnt[BK];        // hist -> exclusive starts (16 KB)
    __shared__ int   wtot[32];
    __shared__ float red[32];

    const int d = blockIdx.x;
    const int t = threadIdx.x;
    const int lane = t & 31, wid = t >> 5;

    // Prefetch query value: overlaps the whole build phase.
    float x = e[t * Dd + d];

    // Prefetch z values (MLP across 4 independent LDGs).
    float v[4];
    #pragma unroll
    for (int i = 0; i < 4; i++) v[i] = g_zt[d * Nn + t + i * 1024];

    // Zero histogram.
    #pragma unroll
    for (int i = 0; i < 4; i++) cnt[t + i * 1024] = 0;
    __syncthreads();

    // ---- single atomic pass: histogram + within-bucket rank ----
    int bk[4], r[4];
    #pragma unroll
    for (int i = 0; i < 4; i++) {
        bk[i] = bucket_of(v[i]);
        r[i]  = atomicAdd(&cnt[bk[i]], 1);
    }
    __syncthreads();

    // ---- block exclusive scan: counts -> exclusive starts (in place) ----
    int c0 = cnt[4 * t], c1 = cnt[4 * t + 1], c2 = cnt[4 * t + 2], c3 = cnt[4 * t + 3];
    int s = c0 + c1 + c2 + c3;
    int inc = s;
    #pragma unroll
    for (int o = 1; o < 32; o <<= 1) {
        int n = __shfl_up_sync(0xFFFFFFFFu, inc, o);
        if (lane >= o) inc += n;
    }
    if (lane == 31) wtot[wid] = inc;
    __syncthreads();
    if (wid == 0) {
        int ws = wtot[lane];
        int wi = ws;
        #pragma unroll
        for (int o = 1; o < 32; o <<= 1) {
            int n = __shfl_up_sync(0xFFFFFFFFu, wi, o);
            if (lane >= o) wi += n;
        }
        wtot[lane] = wi - ws;            // exclusive warp offsets
    }
    __syncthreads();
    int excl = (inc - s) + wtot[wid];
    cnt[4 * t]     = excl;
    cnt[4 * t + 1] = excl + c0;
    cnt[4 * t + 2] = excl + c0 + c1;
    cnt[4 * t + 3] = excl + c0 + c1 + c2;
    __syncthreads();

    // ---- scatter: plain stores, positions are unique by construction ----
    #pragma unroll
    for (int i = 0; i < 4; i++)
        S[cnt[bk[i]] + r[i]] = v[i];
    __syncthreads();

    // ---- query: own bucket + nearest nonempty bucket on each side ----
    int k0 = bucket_of(x);
    int start = cnt[k0];
    int end   = (k0 < BK - 1) ? cnt[k0 + 1] : Nn;

    float best = 1e30f;
    for (int j = start; j < end; j++)
        best = fminf(best, fabsf(S[j] - x));

    if (start > 0) {                     // nearest nonempty bucket below
        float bv = S[start - 1];
        int b = bucket_of(bv);
        int lo = cnt[b];
        for (int j = lo; j < start; j++)
            best = fminf(best, fabsf(S[j] - x));
    }
    if (end < Nn) {                      // nearest nonempty bucket above
        float av = S[end];
        int b = bucket_of(av);
        int hi = (b < BK - 1) ? cnt[b + 1] : Nn;
        for (int j = end; j < hi; j++)
            best = fminf(best, fabsf(S[j] - x));
    }

    float val = best * best * (1.0f / (float)(Mm * Dd));

    // ---- block sum reduce + single atomicAdd ----
    #pragma unroll
    for (int o = 16; o > 0; o >>= 1)
        val += __shfl_xor_sync(0xFFFFFFFFu, val, o);
    if (lane == 0) red[wid] = val;
    __syncthreads();
    if (wid == 0) {
        float sv = red[lane];
        #pragma unroll
        for (int o = 16; o > 0; o >>= 1)
            sv += __shfl_xor_sync(0xFFFFFFFFu, sv, o);
        if (lane == 0) atomicAdd(out, sv);
    }
}

// ---------------------------------------------------------------------------
extern "C" void kernel_launch(void* const* d_in, const int* in_sizes, int n_in,
                              void* d_out, int out_size) {
    const float* z = (const float*)d_in[0];
    const float* e = (const float*)d_in[1];
    const int* idx = (const int*)d_in[2];
    float* out = (float*)d_out;

    k1_prep<<<dim3(Dd / 32, Nn / 32), dim3(32, 32)>>>(z, idx, out);
    k2_nn<<<Dd, 1024>>>(e, out);
}